// round 2
// baseline (speedup 1.0000x reference)
#include <cuda_runtime.h>
#include <cstdint>
#include <cstddef>

#define BDIM 64
#define TDIM 512
#define DDIM 512
#define HDIM 1024
#define ODIM 512
#define G3   3072
#define MROWS 32768            // B*T
#define NCTA_REC 64
#define JCTA 16                // hidden units per recurrence CTA

// Scratch (device globals are the sanctioned no-alloc workaround)
__device__ float g_xall[(size_t)MROWS * G3];     // x projection, 402 MB
__device__ float g_hbuf[2][BDIM * HDIM];         // h ping-pong
__device__ volatile unsigned g_count;            // global barrier counter

__device__ __forceinline__ unsigned f2tf32(float x) {
    unsigned r;
    asm("cvt.rna.tf32.f32 %0, %1;" : "=r"(r) : "f"(x));
    return r;
}

__device__ __forceinline__ void mma_tf32_k4(float* d, unsigned a0, unsigned a1, unsigned b0) {
    asm volatile(
        "mma.sync.aligned.m16n8k4.row.col.f32.tf32.tf32.f32 "
        "{%0,%1,%2,%3}, {%4,%5}, {%6}, {%0,%1,%2,%3};\n"
        : "+f"(d[0]), "+f"(d[1]), "+f"(d[2]), "+f"(d[3])
        : "r"(a0), "r"(a1), "r"(b0));
}

__device__ __forceinline__ float sigmoidf_(float x) {
    return 1.0f / (1.0f + __expf(-x));
}
__device__ __forceinline__ float tanhf_(float x) {
    x = fminf(fmaxf(x, -15.0f), 15.0f);
    float e = __expf(-2.0f * x);
    return (1.0f - e) / (1.0f + e);
}

// ---------------------------------------------------------------------------
// Generic NT GEMM: C[M,N] = A[M,K](rm) * B[N,K](rm)^T + bias[N]
// Tiles: BM=128, BN=128, BK=32; 256 threads; warp grid 4(m) x 2(n), warp tile 32x64.
// tf32 m16n8k4 MMA; smem stored k-major with pad 132 for conflict-free frag loads.
// All dims divisible by tiles for this problem (no predication).
// ---------------------------------------------------------------------------
__global__ __launch_bounds__(256) void gemm_nt_kernel(
    const float* __restrict__ A, const float* __restrict__ B,
    const float* __restrict__ bias, float* __restrict__ C,
    int N, int K)
{
    __shared__ unsigned As[32][132];
    __shared__ unsigned Bs[32][132];
    const int tid  = threadIdx.x;
    const int lane = tid & 31;
    const int warp = tid >> 5;
    const int wm = warp & 3;         // 0..3 -> 32-row slab
    const int wn = warp >> 2;        // 0..1 -> 64-col slab
    const int g = lane >> 2;         // groupID
    const int c = lane & 3;          // threadID_in_group
    const int bm = blockIdx.y, bn = blockIdx.x;
    const float* Ab = A + (size_t)bm * 128 * K;
    const float* Bb = B + (size_t)bn * 128 * K;

    float acc[2][8][4];
#pragma unroll
    for (int i = 0; i < 2; i++)
#pragma unroll
        for (int j = 0; j < 8; j++)
#pragma unroll
            for (int e = 0; e < 4; e++) acc[i][j][e] = 0.0f;

    for (int k0 = 0; k0 < K; k0 += 32) {
        __syncthreads();
#pragma unroll
        for (int p = 0; p < 4; p++) {
            int flat = p * 256 + tid;
            int row = flat >> 3;
            int ks = (flat & 7) * 4;
            float4 va = *(const float4*)(Ab + (size_t)row * K + k0 + ks);
            As[ks + 0][row] = f2tf32(va.x);
            As[ks + 1][row] = f2tf32(va.y);
            As[ks + 2][row] = f2tf32(va.z);
            As[ks + 3][row] = f2tf32(va.w);
            float4 vb = *(const float4*)(Bb + (size_t)row * K + k0 + ks);
            Bs[ks + 0][row] = f2tf32(vb.x);
            Bs[ks + 1][row] = f2tf32(vb.y);
            Bs[ks + 2][row] = f2tf32(vb.z);
            Bs[ks + 3][row] = f2tf32(vb.w);
        }
        __syncthreads();
#pragma unroll
        for (int ks = 0; ks < 32; ks += 4) {
            unsigned a[2][2], b[8];
#pragma unroll
            for (int mt = 0; mt < 2; mt++) {
                int mb = wm * 32 + mt * 16;
                a[mt][0] = As[ks + c][mb + g];
                a[mt][1] = As[ks + c][mb + g + 8];
            }
#pragma unroll
            for (int nt = 0; nt < 8; nt++) b[nt] = Bs[ks + c][wn * 64 + nt * 8 + g];
#pragma unroll
            for (int mt = 0; mt < 2; mt++)
#pragma unroll
                for (int nt = 0; nt < 8; nt++)
                    mma_tf32_k4(acc[mt][nt], a[mt][0], a[mt][1], b[nt]);
        }
    }

#pragma unroll
    for (int mt = 0; mt < 2; mt++) {
        int row = bm * 128 + wm * 32 + mt * 16 + g;
#pragma unroll
        for (int nt = 0; nt < 8; nt++) {
            int col = bn * 128 + wn * 64 + nt * 8 + 2 * c;
            float b0 = bias[col], b1 = bias[col + 1];
            C[(size_t)row * N + col]           = acc[mt][nt][0] + b0;
            C[(size_t)row * N + col + 1]       = acc[mt][nt][1] + b1;
            C[(size_t)(row + 8) * N + col]     = acc[mt][nt][2] + b0;
            C[(size_t)(row + 8) * N + col + 1] = acc[mt][nt][3] + b1;
        }
    }
}

// ---------------------------------------------------------------------------
// Persistent GRU recurrence. 64 CTAs (single wave), 256 threads each.
// CTA b owns hidden units [16b, 16b+16): Wh slice (3 gates x 16 cols x 1024 k)
// lives in SMEM (tf32) for all 512 steps. h ping-pongs in g_hbuf; one global
// barrier per step (atomic counter, monotone target -> no reset race).
// Warp w: m-tile = w&3 (16 batch rows), hidden-half hh = w>>2 (8 units),
// computes all 3 gates for its 16x8 patch so the gate fusion is thread-local.
// ---------------------------------------------------------------------------
extern __shared__ unsigned rec_smem[];   // [49152] Whs + [64*68] hs

__global__ __launch_bounds__(256, 1) void gru_rec_kernel(
    const float* __restrict__ Wh, const float* __restrict__ bh,
    float* __restrict__ hiddens)
{
    unsigned* Whs = rec_smem;             // [hh(2)][gate(3)][k(1024)][n(8)]
    unsigned* hs  = rec_smem + 49152;     // [k(64)][b(64)] stride 68
    const int tid  = threadIdx.x;
    const int lane = tid & 31;
    const int warp = tid >> 5;
    const int mt = warp & 3;
    const int hh = warp >> 2;
    const int mb = mt * 16;
    const int g = lane >> 2, c = lane & 3;
    const int j0 = blockIdx.x * JCTA;

    // Load Wh slice -> SMEM (tf32), once.
    for (int flat = tid; flat < 48 * 1024; flat += 256) {
        int r = flat >> 10, k = flat & 1023;
        int lhh = r / 24, rem = r % 24, gi = rem >> 3, n = rem & 7;
        float v = Wh[(size_t)(gi * HDIM + j0 + lhh * 8 + n) * HDIM + k];
        Whs[((((lhh * 3 + gi) << 10) + k) << 3) + n] = f2tf32(v);
    }

    const int jj = j0 + hh * 8 + 2 * c;   // even output column (hidden unit)
    float bhv[3][2];
#pragma unroll
    for (int gi = 0; gi < 3; gi++) {
        bhv[gi][0] = bh[gi * HDIM + jj];
        bhv[gi][1] = bh[gi * HDIM + jj + 1];
    }
    __syncthreads();

    for (int t = 0; t < TDIM; t++) {
        const float* hr = g_hbuf[t & 1];
        float* hw = g_hbuf[(t & 1) ^ 1];

        float acc[3][4];
#pragma unroll
        for (int gi = 0; gi < 3; gi++)
#pragma unroll
            for (int e = 0; e < 4; e++) acc[gi][e] = 0.0f;

        for (int kk = 0; kk < HDIM; kk += 64) {
            __syncthreads();
#pragma unroll
            for (int p = 0; p < 4; p++) {
                int flat = p * 256 + tid;
                int b = flat >> 4;
                int k4 = (flat & 15) * 4;
                float4 v = *(const float4*)(hr + b * HDIM + kk + k4);
                hs[(k4 + 0) * 68 + b] = f2tf32(v.x);
                hs[(k4 + 1) * 68 + b] = f2tf32(v.y);
                hs[(k4 + 2) * 68 + b] = f2tf32(v.z);
                hs[(k4 + 3) * 68 + b] = f2tf32(v.w);
            }
            __syncthreads();
#pragma unroll
            for (int ks = 0; ks < 64; ks += 4) {
                unsigned a0 = hs[(ks + c) * 68 + mb + g];
                unsigned a1 = hs[(ks + c) * 68 + mb + g + 8];
#pragma unroll
                for (int gi = 0; gi < 3; gi++) {
                    unsigned b0 = Whs[((((hh * 3 + gi) << 10) + kk + ks + c) << 3) + g];
                    mma_tf32_k4(acc[gi], a0, a1, b0);
                }
            }
        }

        // Gate fusion + state update (acc layout: e0:(g,2c) e1:(g,2c+1) e2:(g+8,2c) e3:(g+8,2c+1))
#pragma unroll
        for (int e = 0; e < 4; e++) {
            int b = mb + g + ((e >> 1) << 3);
            int j = jj + (e & 1);
            size_t xi = ((size_t)b * TDIM + t) * G3 + j;
            float hprev = hr[b * HDIM + j];
            float pr = acc[0][e] + bhv[0][e & 1];
            float pu = acc[1][e] + bhv[1][e & 1];
            float pn = acc[2][e] + bhv[2][e & 1];
            float rg = sigmoidf_(g_xall[xi] + pr);
            float ug = sigmoidf_(g_xall[xi + HDIM] + pu);
            float ng = tanhf_(g_xall[xi + 2 * HDIM] + rg * pn);
            float hy = ug * hprev + (1.0f - ug) * ng;
            hw[b * HDIM + j] = hy;
            hiddens[((size_t)b * TDIM + t) * HDIM + j] = hy;
        }

        // Global barrier (monotone counter: target = NCTA*(t+1), reset by init kernel per launch)
        __threadfence();
        __syncthreads();
        if (tid == 0) {
            atomicAdd((unsigned*)&g_count, 1u);
            unsigned target = (unsigned)(t + 1) * NCTA_REC;
            while (g_count < target) { }
        }
        __syncthreads();
        __threadfence();
    }
}

__global__ void rec_init_kernel() {
    int i = blockIdx.x * blockDim.x + threadIdx.x;
    if (i == 0) g_count = 0;
    if (i < BDIM * HDIM) g_hbuf[0][i] = 0.0f;
}

extern "C" void kernel_launch(void* const* d_in, const int* in_sizes, int n_in,
                              void* d_out, int out_size)
{
    (void)in_sizes; (void)n_in; (void)out_size;
    const float* inputs = (const float*)d_in[0];
    const float* Wx = (const float*)d_in[1];
    const float* bx = (const float*)d_in[2];
    const float* Wh = (const float*)d_in[3];
    const float* bh = (const float*)d_in[4];
    const float* Wo = (const float*)d_in[5];
    const float* bo = (const float*)d_in[6];

    float* hiddens = (float*)d_out;                       // (B,T,H)
    float* proj    = hiddens + (size_t)MROWS * HDIM;      // (B,T,O)

    float* xall = nullptr;
    cudaGetSymbolAddress((void**)&xall, g_xall);

    // Phase 0: reset barrier + zero h0
    rec_init_kernel<<<256, 256>>>();

    // Phase 1: x_all = inputs @ Wx^T + bx   (M=32768, N=3072, K=512)
    gemm_nt_kernel<<<dim3(G3 / 128, MROWS / 128), 256>>>(inputs, Wx, bx, xall, G3, DDIM);

    // Phase 2: persistent GRU recurrence -> hiddens (in d_out)
    const int rec_smem_bytes = (49152 + 64 * 68) * 4;     // 214,016 B
    cudaFuncSetAttribute(gru_rec_kernel, cudaFuncAttributeMaxDynamicSharedMemorySize, rec_smem_bytes);
    gru_rec_kernel<<<NCTA_REC, 256, rec_smem_bytes>>>(Wh, bh, hiddens);

    // Phase 3: out = hiddens @ Wo^T + bo   (M=32768, N=512, K=1024)
    gemm_nt_kernel<<<dim3(ODIM / 128, MROWS / 128), 256>>>(hiddens, Wo, bo, proj, ODIM, HDIM);
}

// round 3
// speedup vs baseline: 2.7060x; 2.7060x over previous
#include <cuda_runtime.h>
#include <cstdint>
#include <cstddef>

#define BDIM 64
#define TDIM 512
#define DDIM 512
#define HDIM 1024
#define ODIM 512
#define G3   3072
#define MROWS 32768            // B*T
#define RCTA 128               // recurrence CTAs (single wave)
#define RJ   8                 // hidden units per recurrence CTA

// Scratch (device globals are the sanctioned no-alloc workaround)
__device__ float g_xall[(size_t)MROWS * G3];        // x projection, 402 MB
__device__ float g_hbuf[2][BDIM * HDIM];            // h ping-pong (plain fp32)
__device__ unsigned g_hfrag[2][BDIM * HDIM];        // h ping-pong (tf32, A-fragment-major)
__device__ volatile unsigned g_count;               // global barrier counter

__device__ __forceinline__ unsigned f2tf32(float x) {
    unsigned r;
    asm("cvt.rna.tf32.f32 %0, %1;" : "=r"(r) : "f"(x));
    return r;
}

__device__ __forceinline__ void mma_tf32_k8(float* d,
    unsigned a0, unsigned a1, unsigned a2, unsigned a3,
    unsigned b0, unsigned b1)
{
    asm volatile(
        "mma.sync.aligned.m16n8k8.row.col.f32.tf32.tf32.f32 "
        "{%0,%1,%2,%3}, {%4,%5,%6,%7}, {%8,%9}, {%0,%1,%2,%3};\n"
        : "+f"(d[0]), "+f"(d[1]), "+f"(d[2]), "+f"(d[3])
        : "r"(a0), "r"(a1), "r"(a2), "r"(a3), "r"(b0), "r"(b1));
}

__device__ __forceinline__ float sigmoidf_(float x) {
    return 1.0f / (1.0f + __expf(-x));
}
__device__ __forceinline__ float tanhf_(float x) {
    x = fminf(fmaxf(x, -15.0f), 15.0f);
    float e = __expf(-2.0f * x);
    return (1.0f - e) / (1.0f + e);
}

// ---------------------------------------------------------------------------
// Generic NT GEMM: C[M,N] = A[M,K](rm) * B[N,K](rm)^T + bias[N]
// Tiles: BM=128, BN=128, BK=32; 256 threads; warp grid 4(m) x 2(n).
// tf32 m16n8k8 MMA; smem k-major, pad 132.
// ---------------------------------------------------------------------------
__global__ __launch_bounds__(256) void gemm_nt_kernel(
    const float* __restrict__ A, const float* __restrict__ B,
    const float* __restrict__ bias, float* __restrict__ C,
    int N, int K)
{
    __shared__ unsigned As[32][132];
    __shared__ unsigned Bs[32][132];
    const int tid  = threadIdx.x;
    const int lane = tid & 31;
    const int warp = tid >> 5;
    const int wm = warp & 3;
    const int wn = warp >> 2;
    const int g = lane >> 2;
    const int c = lane & 3;
    const int bm = blockIdx.y, bn = blockIdx.x;
    const float* Ab = A + (size_t)bm * 128 * K;
    const float* Bb = B + (size_t)bn * 128 * K;

    float acc[2][8][4];
#pragma unroll
    for (int i = 0; i < 2; i++)
#pragma unroll
        for (int j = 0; j < 8; j++)
#pragma unroll
            for (int e = 0; e < 4; e++) acc[i][j][e] = 0.0f;

    for (int k0 = 0; k0 < K; k0 += 32) {
        __syncthreads();
#pragma unroll
        for (int p = 0; p < 4; p++) {
            int flat = p * 256 + tid;
            int row = flat >> 3;
            int ks = (flat & 7) * 4;
            float4 va = *(const float4*)(Ab + (size_t)row * K + k0 + ks);
            As[ks + 0][row] = f2tf32(va.x);
            As[ks + 1][row] = f2tf32(va.y);
            As[ks + 2][row] = f2tf32(va.z);
            As[ks + 3][row] = f2tf32(va.w);
            float4 vb = *(const float4*)(Bb + (size_t)row * K + k0 + ks);
            Bs[ks + 0][row] = f2tf32(vb.x);
            Bs[ks + 1][row] = f2tf32(vb.y);
            Bs[ks + 2][row] = f2tf32(vb.z);
            Bs[ks + 3][row] = f2tf32(vb.w);
        }
        __syncthreads();
#pragma unroll
        for (int ks = 0; ks < 32; ks += 8) {
            unsigned a[2][4], b[8][2];
#pragma unroll
            for (int mt = 0; mt < 2; mt++) {
                int mb = wm * 32 + mt * 16;
                a[mt][0] = As[ks + c][mb + g];
                a[mt][1] = As[ks + c][mb + g + 8];
                a[mt][2] = As[ks + c + 4][mb + g];
                a[mt][3] = As[ks + c + 4][mb + g + 8];
            }
#pragma unroll
            for (int nt = 0; nt < 8; nt++) {
                int col = wn * 64 + nt * 8 + g;
                b[nt][0] = Bs[ks + c][col];
                b[nt][1] = Bs[ks + c + 4][col];
            }
#pragma unroll
            for (int mt = 0; mt < 2; mt++)
#pragma unroll
                for (int nt = 0; nt < 8; nt++)
                    mma_tf32_k8(acc[mt][nt], a[mt][0], a[mt][1], a[mt][2], a[mt][3],
                                b[nt][0], b[nt][1]);
        }
    }

#pragma unroll
    for (int mt = 0; mt < 2; mt++) {
        int row = bm * 128 + wm * 32 + mt * 16 + g;
#pragma unroll
        for (int nt = 0; nt < 8; nt++) {
            int col = bn * 128 + wn * 64 + nt * 8 + 2 * c;
            float b0 = bias[col], b1 = bias[col + 1];
            C[(size_t)row * N + col]           = acc[mt][nt][0] + b0;
            C[(size_t)row * N + col + 1]       = acc[mt][nt][1] + b1;
            C[(size_t)(row + 8) * N + col]     = acc[mt][nt][2] + b0;
            C[(size_t)(row + 8) * N + col + 1] = acc[mt][nt][3] + b1;
        }
    }
}

// ---------------------------------------------------------------------------
// Persistent GRU recurrence. 128 CTAs (single wave), 256 threads each.
// CTA owns RJ=8 hidden units -> 24 output cols = one n8 MMA tile per gate.
// Wh slice resident in SMEM in B-fragment order (LDS.64 per gate per k8-iter).
// h_t lives in GMEM in A-fragment order (tf32): one LDG.128 per k8-iter.
// Warps: mt=warp&3 (16 batch rows), kh=warp>>2 (K half); SMEM reduction of
// the two K halves; epilogue + h write by kh==0 warps; one global barrier/step.
// ---------------------------------------------------------------------------
extern __shared__ unsigned rec_smem[];   // Whs[24576] + red[1536]

__global__ __launch_bounds__(256, 1) void gru_rec_kernel(
    const float* __restrict__ Wh, const float* __restrict__ bh,
    float* __restrict__ hiddens)
{
    unsigned* Whs = rec_smem;                       // [kb(128)][gate(3)][lane(32)][2]
    float* red = (float*)(rec_smem + 24576);        // [mt(4)][lane(32)][12]
    const int tid  = threadIdx.x;
    const int lane = tid & 31;
    const int warp = tid >> 5;
    const int mt = warp & 3;
    const int kh = warp >> 2;
    const int g = lane >> 2, c = lane & 3;
    const int j0 = blockIdx.x * RJ;

    // Load Wh slice -> SMEM in B-fragment order (tf32), once.
    for (int flat = tid; flat < 128 * 3 * 32; flat += 256) {
        int kb = flat / 96, rem = flat % 96;
        int gi = rem >> 5, ln = rem & 31;
        int gg = ln >> 2, cc = ln & 3;
        const float* wp = Wh + (size_t)(gi * HDIM + j0 + gg) * HDIM + kb * 8 + cc;
        Whs[flat * 2 + 0] = f2tf32(wp[0]);
        Whs[flat * 2 + 1] = f2tf32(wp[4]);
    }

    const int jj = j0 + 2 * c;
    const int b0r = mt * 16 + g, b1r = b0r + 8;
    float bh0[3], bh1[3];
#pragma unroll
    for (int gi = 0; gi < 3; gi++) {
        bh0[gi] = bh[gi * HDIM + jj];
        bh1[gi] = bh[gi * HDIM + jj + 1];
    }
    __syncthreads();

    for (int t = 0; t < TDIM; t++) {
        const int pp = t & 1;
        // Prefetch x_t and h_prev (DRAM latency hidden behind MMA loop)
        float2 xv[3][2], hp0, hp1;
        if (kh == 0) {
#pragma unroll
            for (int gi = 0; gi < 3; gi++) {
                xv[gi][0] = *(const float2*)&g_xall[((size_t)b0r * TDIM + t) * G3 + gi * HDIM + jj];
                xv[gi][1] = *(const float2*)&g_xall[((size_t)b1r * TDIM + t) * G3 + gi * HDIM + jj];
            }
            hp0 = *(const float2*)&g_hbuf[pp][b0r * HDIM + jj];
            hp1 = *(const float2*)&g_hbuf[pp][b1r * HDIM + jj];
        }

        float acc[3][4];
#pragma unroll
        for (int gi = 0; gi < 3; gi++)
#pragma unroll
            for (int e = 0; e < 4; e++) acc[gi][e] = 0.0f;

        const unsigned* __restrict__ hf = g_hfrag[pp];
#pragma unroll 4
        for (int it = 0; it < 64; it++) {
            int kb = kh * 64 + it;
            uint4 a = *(const uint4*)(hf + (((kb * 4 + mt) * 32 + lane) << 2));
#pragma unroll
            for (int gi = 0; gi < 3; gi++) {
                uint2 b = *(const uint2*)(Whs + ((((kb * 3 + gi) << 5) + lane) << 1));
                mma_tf32_k8(acc[gi], a.x, a.y, a.z, a.w, b.x, b.y);
            }
        }

        if (kh == 1) {
            float* rp = red + (mt * 32 + lane) * 12;
#pragma unroll
            for (int gi = 0; gi < 3; gi++)
#pragma unroll
                for (int e = 0; e < 4; e++) rp[gi * 4 + e] = acc[gi][e];
        }
        __syncthreads();

        if (kh == 0) {
            const float* rp = red + (mt * 32 + lane) * 12;
            float hy[4];
#pragma unroll
            for (int gi = 0; gi < 3; gi++)
#pragma unroll
                for (int e = 0; e < 4; e++) acc[gi][e] += rp[gi * 4 + e];
#pragma unroll
            for (int e = 0; e < 4; e++) {
                int part = e & 1, row = e >> 1;
                float xr = part ? xv[0][row].y : xv[0][row].x;
                float xu = part ? xv[1][row].y : xv[1][row].x;
                float xn = part ? xv[2][row].y : xv[2][row].x;
                float hp = row ? (part ? hp1.y : hp1.x) : (part ? hp0.y : hp0.x);
                float pr = acc[0][e] + (part ? bh1[0] : bh0[0]);
                float pu = acc[1][e] + (part ? bh1[1] : bh0[1]);
                float pn = acc[2][e] + (part ? bh1[2] : bh0[2]);
                float rg = sigmoidf_(xr + pr);
                float ug = sigmoidf_(xu + pu);
                float ng = tanhf_(xn + rg * pn);
                hy[e] = ug * hp + (1.0f - ug) * ng;
            }
            // plain h (fp32) + hiddens output
            *(float2*)&g_hbuf[pp ^ 1][b0r * HDIM + jj] = make_float2(hy[0], hy[1]);
            *(float2*)&g_hbuf[pp ^ 1][b1r * HDIM + jj] = make_float2(hy[2], hy[3]);
            *(float2*)&hiddens[((size_t)b0r * TDIM + t) * HDIM + jj] = make_float2(hy[0], hy[1]);
            *(float2*)&hiddens[((size_t)b1r * TDIM + t) * HDIM + jj] = make_float2(hy[2], hy[3]);
            // fragment-major h (tf32) for next step's MMA
            unsigned* nf = g_hfrag[pp ^ 1];
            const int kbt = j0 >> 3;
#pragma unroll
            for (int e = 0; e < 4; e++) {
                int part = e & 1, row = e >> 1;
                int kpos = 2 * c + part;
                int reg = row + 2 * (kpos >> 2);
                int lnt = (g << 2) | (kpos & 3);
                nf[(((kbt * 4 + mt) * 32 + lnt) << 2) + reg] = f2tf32(hy[e]);
            }
        }

        // Global barrier (monotone counter; release fence before arrive,
        // acquire poll after)
        __threadfence();
        __syncthreads();
        if (tid == 0) {
            atomicAdd((unsigned*)&g_count, 1u);
            unsigned target = (unsigned)(t + 1) * RCTA;
            unsigned v;
            do {
                asm volatile("ld.global.acquire.gpu.u32 %0, [%1];"
                             : "=r"(v) : "l"((const unsigned*)&g_count) : "memory");
            } while (v < target);
        }
        __syncthreads();
    }
}

__global__ void rec_init_kernel() {
    int i = blockIdx.x * blockDim.x + threadIdx.x;
    if (i == 0) g_count = 0;
    if (i < BDIM * HDIM) {
        g_hbuf[0][i] = 0.0f;
        g_hfrag[0][i] = 0u;
    }
}

extern "C" void kernel_launch(void* const* d_in, const int* in_sizes, int n_in,
                              void* d_out, int out_size)
{
    (void)in_sizes; (void)n_in; (void)out_size;
    const float* inputs = (const float*)d_in[0];
    const float* Wx = (const float*)d_in[1];
    const float* bx = (const float*)d_in[2];
    const float* Wh = (const float*)d_in[3];
    const float* bh = (const float*)d_in[4];
    const float* Wo = (const float*)d_in[5];
    const float* bo = (const float*)d_in[6];

    float* hiddens = (float*)d_out;                       // (B,T,H)
    float* proj    = hiddens + (size_t)MROWS * HDIM;      // (B,T,O)

    float* xall = nullptr;
    cudaGetSymbolAddress((void**)&xall, g_xall);

    // Phase 0: reset barrier + zero h0 (both layouts)
    rec_init_kernel<<<256, 256>>>();

    // Phase 1: x_all = inputs @ Wx^T + bx   (M=32768, N=3072, K=512)
    gemm_nt_kernel<<<dim3(G3 / 128, MROWS / 128), 256>>>(inputs, Wx, bx, xall, G3, DDIM);

    // Phase 2: persistent GRU recurrence -> hiddens (in d_out)
    const int rec_smem_bytes = (24576 + 1536) * 4;        // 104,448 B
    cudaFuncSetAttribute(gru_rec_kernel, cudaFuncAttributeMaxDynamicSharedMemorySize, rec_smem_bytes);
    gru_rec_kernel<<<RCTA, 256, rec_smem_bytes>>>(Wh, bh, hiddens);

    // Phase 3: out = hiddens @ Wo^T + bo   (M=32768, N=512, K=1024)
    gemm_nt_kernel<<<dim3(ODIM / 128, MROWS / 128), 256>>>(hiddens, Wo, bo, proj, ODIM, HDIM);
}